// round 8
// baseline (speedup 1.0000x reference)
#include <cuda_runtime.h>

// SoftAttentionAlignment: two symmetric attention passes, fp32 flash-style,
// packed fma.rn.f32x2 for 2x FMA issue rate on sm_103a CUDA cores.
//
// B=8, L=2048, D=128. Pass 0: Q=x1, K=V=x2 -> q1_combined.
//                     Pass 1: Q=x2, K=V=x1 -> q2_combined.
// out = [q1_combined flat | q2_combined flat], rows of 4*D=512 floats:
//       [x, o, x-o, x*o].

#define BQ      64
#define BK      64
#define DIM     128
#define LSEQ    2048
#define BATCH   8
#define QPITCH  132   // floats; 528B row -> conflict-free broadcast loads
#define KPITCH  132
#define PPITCH  68    // floats; 272B row, float4-aligned

__device__ __forceinline__ float2 ffma2(float2 a, float2 b, float2 c) {
    unsigned long long du;
    asm("fma.rn.f32x2 %0, %1, %2, %3;"
        : "=l"(du)
        : "l"(*reinterpret_cast<const unsigned long long*>(&a)),
          "l"(*reinterpret_cast<const unsigned long long*>(&b)),
          "l"(*reinterpret_cast<const unsigned long long*>(&c)));
    return *reinterpret_cast<float2*>(&du);
}

extern __shared__ float smem_dyn[];

__global__ void __launch_bounds__(256, 2)
soft_attn_align_kernel(const float* __restrict__ x1,
                       const float* __restrict__ x2,
                       float* __restrict__ out)
{
    float* Qs = smem_dyn;                       // [BQ][QPITCH]
    float* Ks = Qs + BQ * QPITCH;               // [BK][KPITCH]
    float* Ps = Ks + BK * KPITCH;               // [BQ][PPITCH]

    const int tid  = threadIdx.x;
    const int ty   = tid >> 4;    // 0..15 : row group (rows 4*ty .. 4*ty+3)
    const int tx   = tid & 15;    // 0..15 : col group
    const int pass = blockIdx.z;
    const int b    = blockIdx.y;
    const int qt   = blockIdx.x;

    const float* Qg = (pass == 0 ? x1 : x2) + ((size_t)b * LSEQ + (size_t)qt * BQ) * DIM;
    const float* Kg = (pass == 0 ? x2 : x1) + (size_t)b * LSEQ * DIM;
    float* Og = out + ((size_t)pass * BATCH + b) * LSEQ * (4 * DIM)
                    + (size_t)(qt * BQ) * (4 * DIM);

    // ---- load Q tile (coalesced float4) ----
    for (int t = tid; t < BQ * (DIM / 4); t += 256) {
        int row = t >> 5, c4 = t & 31;
        float4 v = reinterpret_cast<const float4*>(Qg)[row * (DIM / 4) + c4];
        *reinterpret_cast<float4*>(&Qs[row * QPITCH + c4 * 4]) = v;
    }

    // Output accumulator: rows 4*ty+r, col pairs {4tx,4tx+1},{4tx+2,4tx+3},
    // {4tx+64,65},{4tx+66,67}
    float2 o2[4][4];
    #pragma unroll
    for (int r = 0; r < 4; r++)
        #pragma unroll
        for (int h = 0; h < 4; h++) o2[r][h] = make_float2(0.f, 0.f);

    float mrow[4], lrow[4];
    #pragma unroll
    for (int r = 0; r < 4; r++) { mrow[r] = -1e30f; lrow[r] = 0.f; }

    for (int kt = 0; kt < LSEQ / BK; kt++) {
        __syncthreads();   // previous iteration's PV done reading Ks
        {
            const float* Kt = Kg + (size_t)kt * BK * DIM;
            for (int t = tid; t < BK * (DIM / 4); t += 256) {
                int row = t >> 5, c4 = t & 31;
                float4 v = reinterpret_cast<const float4*>(Kt)[row * (DIM / 4) + c4];
                *reinterpret_cast<float4*>(&Ks[row * KPITCH + c4 * 4]) = v;
            }
        }
        __syncthreads();

        // ---- S = Q K^T : thread owns S[4ty+r][tx+16f] ----
        float2 acc[4][4];
        #pragma unroll
        for (int r = 0; r < 4; r++)
            #pragma unroll
            for (int f = 0; f < 4; f++) acc[r][f] = make_float2(0.f, 0.f);

        #pragma unroll 1
        for (int d = 0; d < DIM; d += 4) {
            float4 q4[4], k4[4];
            #pragma unroll
            for (int r = 0; r < 4; r++)
                q4[r] = *reinterpret_cast<const float4*>(&Qs[(4 * ty + r) * QPITCH + d]);
            #pragma unroll
            for (int f = 0; f < 4; f++)
                k4[f] = *reinterpret_cast<const float4*>(&Ks[(tx + 16 * f) * KPITCH + d]);
            #pragma unroll
            for (int r = 0; r < 4; r++) {
                float2 qa = make_float2(q4[r].x, q4[r].y);
                float2 qb = make_float2(q4[r].z, q4[r].w);
                #pragma unroll
                for (int f = 0; f < 4; f++) {
                    acc[r][f] = ffma2(qa, make_float2(k4[f].x, k4[f].y), acc[r][f]);
                    acc[r][f] = ffma2(qb, make_float2(k4[f].z, k4[f].w), acc[r][f]);
                }
            }
        }

        // ---- online softmax over the 64 cols of this tile ----
        #pragma unroll
        for (int r = 0; r < 4; r++) {
            float s0 = acc[r][0].x + acc[r][0].y;
            float s1 = acc[r][1].x + acc[r][1].y;
            float s2 = acc[r][2].x + acc[r][2].y;
            float s3 = acc[r][3].x + acc[r][3].y;
            float mt = fmaxf(fmaxf(s0, s1), fmaxf(s2, s3));
            #pragma unroll
            for (int off = 8; off >= 1; off >>= 1)
                mt = fmaxf(mt, __shfl_xor_sync(0xffffffffu, mt, off));
            float mnew  = fmaxf(mrow[r], mt);
            float scale = __expf(mrow[r] - mnew);
            mrow[r] = mnew;

            float p0 = __expf(s0 - mnew);
            float p1 = __expf(s1 - mnew);
            float p2 = __expf(s2 - mnew);
            float p3 = __expf(s3 - mnew);
            float* prow = &Ps[(4 * ty + r) * PPITCH + tx];
            prow[0]  = p0;  prow[16] = p1;  prow[32] = p2;  prow[48] = p3;
            float ps = (p0 + p1) + (p2 + p3);
            #pragma unroll
            for (int off = 8; off >= 1; off >>= 1)
                ps += __shfl_xor_sync(0xffffffffu, ps, off);
            lrow[r] = lrow[r] * scale + ps;
            #pragma unroll
            for (int h = 0; h < 4; h++) {
                o2[r][h].x *= scale;
                o2[r][h].y *= scale;
            }
        }
        // P rows 8w..8w+7 are written and read only by warp w:
        __syncwarp();

        // ---- O += P * K ----
        #pragma unroll 1
        for (int j = 0; j < BK; j += 4) {
            float4 p4[4];
            #pragma unroll
            for (int r = 0; r < 4; r++)
                p4[r] = *reinterpret_cast<const float4*>(&Ps[(4 * ty + r) * PPITCH + j]);
            #pragma unroll
            for (int jj = 0; jj < 4; jj++) {
                float4 ka = *reinterpret_cast<const float4*>(&Ks[(j + jj) * KPITCH + 4 * tx]);
                float4 kb = *reinterpret_cast<const float4*>(&Ks[(j + jj) * KPITCH + 4 * tx + 64]);
                float2 ka0 = make_float2(ka.x, ka.y), ka1 = make_float2(ka.z, ka.w);
                float2 kb0 = make_float2(kb.x, kb.y), kb1 = make_float2(kb.z, kb.w);
                #pragma unroll
                for (int r = 0; r < 4; r++) {
                    float pr = (jj == 0) ? p4[r].x : (jj == 1) ? p4[r].y
                             : (jj == 2) ? p4[r].z : p4[r].w;
                    float2 pp = make_float2(pr, pr);
                    o2[r][0] = ffma2(pp, ka0, o2[r][0]);
                    o2[r][1] = ffma2(pp, ka1, o2[r][1]);
                    o2[r][2] = ffma2(pp, kb0, o2[r][2]);
                    o2[r][3] = ffma2(pp, kb1, o2[r][3]);
                }
            }
        }
    }

    // ---- epilogue: out row = [x, o, x-o, x*o], 512 floats ----
    #pragma unroll
    for (int r = 0; r < 4; r++) {
        float inv = 1.0f / lrow[r];
        int row = 4 * ty + r;
        float4 xa = *reinterpret_cast<const float4*>(&Qs[row * QPITCH + 4 * tx]);
        float4 xb = *reinterpret_cast<const float4*>(&Qs[row * QPITCH + 4 * tx + 64]);
        float4 oa = make_float4(o2[r][0].x * inv, o2[r][0].y * inv,
                                o2[r][1].x * inv, o2[r][1].y * inv);
        float4 ob = make_float4(o2[r][2].x * inv, o2[r][2].y * inv,
                                o2[r][3].x * inv, o2[r][3].y * inv);
        float4* v = reinterpret_cast<float4*>(Og + (size_t)row * (4 * DIM));
        v[tx]       = xa;   // x, cols 4tx..
        v[16 + tx]  = xb;   // x, cols 64+4tx..
        v[32 + tx]  = oa;   // o
        v[48 + tx]  = ob;
        v[64 + tx]  = make_float4(xa.x - oa.x, xa.y - oa.y, xa.z - oa.z, xa.w - oa.w);
        v[80 + tx]  = make_float4(xb.x - ob.x, xb.y - ob.y, xb.z - ob.z, xb.w - ob.w);
        v[96 + tx]  = make_float4(xa.x * oa.x, xa.y * oa.y, xa.z * oa.z, xa.w * oa.w);
        v[112 + tx] = make_float4(xb.x * ob.x, xb.y * ob.y, xb.z * ob.z, xb.w * ob.w);
    }
}

extern "C" void kernel_launch(void* const* d_in, const int* in_sizes, int n_in,
                              void* d_out, int out_size) {
    (void)in_sizes; (void)n_in; (void)out_size;
    const float* x1 = (const float*)d_in[0];
    const float* x2 = (const float*)d_in[1];
    float* out = (float*)d_out;

    const size_t smem_bytes =
        (size_t)(BQ * QPITCH + BK * KPITCH + BQ * PPITCH) * sizeof(float); // 84992

    cudaFuncSetAttribute(soft_attn_align_kernel,
                         cudaFuncAttributeMaxDynamicSharedMemorySize,
                         (int)smem_bytes);

    dim3 grid(LSEQ / BQ, BATCH, 2);   // 32 q-tiles x 8 batches x 2 passes
    soft_attn_align_kernel<<<grid, 256, smem_bytes>>>(x1, x2, out);
}

// round 9
// speedup vs baseline: 1.0004x; 1.0004x over previous
#include <cuda_runtime.h>

// SoftAttentionAlignment: two symmetric attention passes, fp32 flash-style,
// packed fma.rn.f32x2 for 2x FMA issue rate on sm_103a CUDA cores.
//
// B=8, L=2048, D=128. Pass 0: Q=x1, K=V=x2 -> q1_combined.
//                     Pass 1: Q=x2, K=V=x1 -> q2_combined.
// out = [q1_combined flat | q2_combined flat], rows of 4*D=512 floats:
//       [x, o, x-o, x*o].

#define BQ      64
#define BK      64
#define DIM     128
#define LSEQ    2048
#define BATCH   8
#define QPITCH  132   // floats; 528B row -> conflict-free broadcast loads
#define KPITCH  132
#define PPITCH  68    // floats; 272B row, float4-aligned

__device__ __forceinline__ float2 ffma2(float2 a, float2 b, float2 c) {
    unsigned long long du;
    asm("fma.rn.f32x2 %0, %1, %2, %3;"
        : "=l"(du)
        : "l"(*reinterpret_cast<const unsigned long long*>(&a)),
          "l"(*reinterpret_cast<const unsigned long long*>(&b)),
          "l"(*reinterpret_cast<const unsigned long long*>(&c)));
    return *reinterpret_cast<float2*>(&du);
}

extern __shared__ float smem_dyn[];

__global__ void __launch_bounds__(256, 2)
soft_attn_align_kernel(const float* __restrict__ x1,
                       const float* __restrict__ x2,
                       float* __restrict__ out)
{
    float* Qs = smem_dyn;                       // [BQ][QPITCH]
    float* Ks = Qs + BQ * QPITCH;               // [BK][KPITCH]
    float* Ps = Ks + BK * KPITCH;               // [BQ][PPITCH]

    const int tid  = threadIdx.x;
    const int ty   = tid >> 4;    // 0..15 : row group (rows 4*ty .. 4*ty+3)
    const int tx   = tid & 15;    // 0..15 : col group
    const int pass = blockIdx.z;
    const int b    = blockIdx.y;
    const int qt   = blockIdx.x;

    const float* Qg = (pass == 0 ? x1 : x2) + ((size_t)b * LSEQ + (size_t)qt * BQ) * DIM;
    const float* Kg = (pass == 0 ? x2 : x1) + (size_t)b * LSEQ * DIM;
    float* Og = out + ((size_t)pass * BATCH + b) * LSEQ * (4 * DIM)
                    + (size_t)(qt * BQ) * (4 * DIM);

    // ---- load Q tile (coalesced float4) ----
    for (int t = tid; t < BQ * (DIM / 4); t += 256) {
        int row = t >> 5, c4 = t & 31;
        float4 v = reinterpret_cast<const float4*>(Qg)[row * (DIM / 4) + c4];
        *reinterpret_cast<float4*>(&Qs[row * QPITCH + c4 * 4]) = v;
    }

    // Output accumulator: rows 4*ty+r, col pairs {4tx,4tx+1},{4tx+2,4tx+3},
    // {4tx+64,65},{4tx+66,67}
    float2 o2[4][4];
    #pragma unroll
    for (int r = 0; r < 4; r++)
        #pragma unroll
        for (int h = 0; h < 4; h++) o2[r][h] = make_float2(0.f, 0.f);

    float mrow[4], lrow[4];
    #pragma unroll
    for (int r = 0; r < 4; r++) { mrow[r] = -1e30f; lrow[r] = 0.f; }

    for (int kt = 0; kt < LSEQ / BK; kt++) {
        __syncthreads();   // previous iteration's PV done reading Ks
        {
            const float* Kt = Kg + (size_t)kt * BK * DIM;
            for (int t = tid; t < BK * (DIM / 4); t += 256) {
                int row = t >> 5, c4 = t & 31;
                float4 v = reinterpret_cast<const float4*>(Kt)[row * (DIM / 4) + c4];
                *reinterpret_cast<float4*>(&Ks[row * KPITCH + c4 * 4]) = v;
            }
        }
        __syncthreads();

        // ---- S = Q K^T : thread owns S[4ty+r][tx+16f] ----
        float2 acc[4][4];
        #pragma unroll
        for (int r = 0; r < 4; r++)
            #pragma unroll
            for (int f = 0; f < 4; f++) acc[r][f] = make_float2(0.f, 0.f);

        #pragma unroll 1
        for (int d = 0; d < DIM; d += 4) {
            float4 q4[4], k4[4];
            #pragma unroll
            for (int r = 0; r < 4; r++)
                q4[r] = *reinterpret_cast<const float4*>(&Qs[(4 * ty + r) * QPITCH + d]);
            #pragma unroll
            for (int f = 0; f < 4; f++)
                k4[f] = *reinterpret_cast<const float4*>(&Ks[(tx + 16 * f) * KPITCH + d]);
            #pragma unroll
            for (int r = 0; r < 4; r++) {
                float2 qa = make_float2(q4[r].x, q4[r].y);
                float2 qb = make_float2(q4[r].z, q4[r].w);
                #pragma unroll
                for (int f = 0; f < 4; f++) {
                    acc[r][f] = ffma2(qa, make_float2(k4[f].x, k4[f].y), acc[r][f]);
                    acc[r][f] = ffma2(qb, make_float2(k4[f].z, k4[f].w), acc[r][f]);
                }
            }
        }

        // ---- online softmax over the 64 cols of this tile ----
        #pragma unroll
        for (int r = 0; r < 4; r++) {
            float s0 = acc[r][0].x + acc[r][0].y;
            float s1 = acc[r][1].x + acc[r][1].y;
            float s2 = acc[r][2].x + acc[r][2].y;
            float s3 = acc[r][3].x + acc[r][3].y;
            float mt = fmaxf(fmaxf(s0, s1), fmaxf(s2, s3));
            #pragma unroll
            for (int off = 8; off >= 1; off >>= 1)
                mt = fmaxf(mt, __shfl_xor_sync(0xffffffffu, mt, off));
            float mnew  = fmaxf(mrow[r], mt);
            float scale = __expf(mrow[r] - mnew);
            mrow[r] = mnew;

            float p0 = __expf(s0 - mnew);
            float p1 = __expf(s1 - mnew);
            float p2 = __expf(s2 - mnew);
            float p3 = __expf(s3 - mnew);
            float* prow = &Ps[(4 * ty + r) * PPITCH + tx];
            prow[0]  = p0;  prow[16] = p1;  prow[32] = p2;  prow[48] = p3;
            float ps = (p0 + p1) + (p2 + p3);
            #pragma unroll
            for (int off = 8; off >= 1; off >>= 1)
                ps += __shfl_xor_sync(0xffffffffu, ps, off);
            lrow[r] = lrow[r] * scale + ps;
            #pragma unroll
            for (int h = 0; h < 4; h++) {
                o2[r][h].x *= scale;
                o2[r][h].y *= scale;
            }
        }
        // P rows 8w..8w+7 are written and read only by warp w:
        __syncwarp();

        // ---- O += P * K ----
        #pragma unroll 1
        for (int j = 0; j < BK; j += 4) {
            float4 p4[4];
            #pragma unroll
            for (int r = 0; r < 4; r++)
                p4[r] = *reinterpret_cast<const float4*>(&Ps[(4 * ty + r) * PPITCH + j]);
            #pragma unroll
            for (int jj = 0; jj < 4; jj++) {
                float4 ka = *reinterpret_cast<const float4*>(&Ks[(j + jj) * KPITCH + 4 * tx]);
                float4 kb = *reinterpret_cast<const float4*>(&Ks[(j + jj) * KPITCH + 4 * tx + 64]);
                float2 ka0 = make_float2(ka.x, ka.y), ka1 = make_float2(ka.z, ka.w);
                float2 kb0 = make_float2(kb.x, kb.y), kb1 = make_float2(kb.z, kb.w);
                #pragma unroll
                for (int r = 0; r < 4; r++) {
                    float pr = (jj == 0) ? p4[r].x : (jj == 1) ? p4[r].y
                             : (jj == 2) ? p4[r].z : p4[r].w;
                    float2 pp = make_float2(pr, pr);
                    o2[r][0] = ffma2(pp, ka0, o2[r][0]);
                    o2[r][1] = ffma2(pp, ka1, o2[r][1]);
                    o2[r][2] = ffma2(pp, kb0, o2[r][2]);
                    o2[r][3] = ffma2(pp, kb1, o2[r][3]);
                }
            }
        }
    }

    // ---- epilogue: out row = [x, o, x-o, x*o], 512 floats ----
    #pragma unroll
    for (int r = 0; r < 4; r++) {
        float inv = 1.0f / lrow[r];
        int row = 4 * ty + r;
        float4 xa = *reinterpret_cast<const float4*>(&Qs[row * QPITCH + 4 * tx]);
        float4 xb = *reinterpret_cast<const float4*>(&Qs[row * QPITCH + 4 * tx + 64]);
        float4 oa = make_float4(o2[r][0].x * inv, o2[r][0].y * inv,
                                o2[r][1].x * inv, o2[r][1].y * inv);
        float4 ob = make_float4(o2[r][2].x * inv, o2[r][2].y * inv,
                                o2[r][3].x * inv, o2[r][3].y * inv);
        float4* v = reinterpret_cast<float4*>(Og + (size_t)row * (4 * DIM));
        v[tx]       = xa;   // x, cols 4tx..
        v[16 + tx]  = xb;   // x, cols 64+4tx..
        v[32 + tx]  = oa;   // o
        v[48 + tx]  = ob;
        v[64 + tx]  = make_float4(xa.x - oa.x, xa.y - oa.y, xa.z - oa.z, xa.w - oa.w);
        v[80 + tx]  = make_float4(xb.x - ob.x, xb.y - ob.y, xb.z - ob.z, xb.w - ob.w);
        v[96 + tx]  = make_float4(xa.x * oa.x, xa.y * oa.y, xa.z * oa.z, xa.w * oa.w);
        v[112 + tx] = make_float4(xb.x * ob.x, xb.y * ob.y, xb.z * ob.z, xb.w * ob.w);
    }
}

extern "C" void kernel_launch(void* const* d_in, const int* in_sizes, int n_in,
                              void* d_out, int out_size) {
    (void)in_sizes; (void)n_in; (void)out_size;
    const float* x1 = (const float*)d_in[0];
    const float* x2 = (const float*)d_in[1];
    float* out = (float*)d_out;

    const size_t smem_bytes =
        (size_t)(BQ * QPITCH + BK * KPITCH + BQ * PPITCH) * sizeof(float); // 84992

    cudaFuncSetAttribute(soft_attn_align_kernel,
                         cudaFuncAttributeMaxDynamicSharedMemorySize,
                         (int)smem_bytes);

    dim3 grid(LSEQ / BQ, BATCH, 2);   // 32 q-tiles x 8 batches x 2 passes
    soft_attn_align_kernel<<<grid, 256, smem_bytes>>>(x1, x2, out);
}